// round 11
// baseline (speedup 1.0000x reference)
#include <cuda_runtime.h>
#include <cuda_bf16.h>
#include <cstdint>

// Antecedent firing strengths:
//   out[s][r] = exp( sum_{d=0..7} log_mv[s, digit_d(r), d] )
// digit_d(r) = (r >> 2*(7-d)) & 3  (base-4 expansion == _fuco_frb rows).
//
// Factorization: r = hi*256 + lo (4 digits each, 4^4 = 256):
//   out[s][r] = eA[hi] * eB[lo]
// 512 exps per CTA (128x fewer than naive); fs_ind gather eliminated by
// arithmetic digit decode. Main loop: register-resident eA/eB, 8
// independent FMUL4 + STG.128 groups -> pure streaming stores.
//
// FINAL (R6 config; best measured kernel 20.38us, dur 23.04us best).
// R4-R10 established the binder is the fixed 134MB output stream at the
// path-independent chip-level LTS/HBM write ceiling (~6.5 TB/s):
// invariant to store width (v4/v8), cache policy (stcs/plain), grid
// shape (1024/2048/4096), occupancy (57-83%), and hot-loop smem traffic.
// ~94% of the achievable store ceiling; residual dur variation is
// harness replay noise (identical-code samples 23.04/24.13/23.94us).

constexpr int IN_DIM  = 8;
constexpr int NUM_FS  = 4;
constexpr int NUM_SAM = 512;
constexpr int HALF    = 256;     // 4^4
constexpr int RULES   = 65536;   // 4^8
constexpr int THREADS = 256;
constexpr int SLICES  = 8;                        // CTAs per sample
constexpr int VECS    = RULES / 4;                // 16384 float4 per sample
constexpr int VECS_PER_SLICE = VECS / SLICES;     // 2048
constexpr int ITERS   = VECS_PER_SLICE / THREADS; // 8

__global__ __launch_bounds__(THREADS)
void antecedent_kernel(const float* __restrict__ x,      // [512, 8]
                       const float* __restrict__ center, // [4, 8]
                       const float* __restrict__ spread, // [4, 8]
                       float* __restrict__ out)          // [512, 65536]
{
    __shared__ float lm[NUM_FS * IN_DIM];
    __shared__ __align__(16) float eA[HALF];
    __shared__ __align__(16) float eB[HALF];

    const int s     = blockIdx.x >> 3;      // sample
    const int slice = blockIdx.x & 7;       // eighth of the sample's output
    const int tid   = threadIdx.x;

    // --- per-sample log membership table (32 values) ---
    if (tid < NUM_FS * IN_DIM) {
        const int f = tid / IN_DIM;
        const int d = tid % IN_DIM;
        const float xv = x[s * IN_DIM + d];
        const float c  = center[f * IN_DIM + d];
        const float sp = spread[f * IN_DIM + d];
        const float df = xv - c;
        lm[f * IN_DIM + d] = -(df * df) / (2.0f * sp * sp);
    }
    __syncthreads();

    // --- factorized half-sums over 4 digits each ---
    if (tid < HALF) {
        const int i  = tid;
        const int g0 = (i >> 6) & 3;
        const int g1 = (i >> 4) & 3;
        const int g2 = (i >> 2) & 3;
        const int g3 =  i       & 3;
        const float a = lm[g0 * IN_DIM + 0] + lm[g1 * IN_DIM + 1]
                      + lm[g2 * IN_DIM + 2] + lm[g3 * IN_DIM + 3];
        const float b = lm[g0 * IN_DIM + 4] + lm[g1 * IN_DIM + 5]
                      + lm[g2 * IN_DIM + 6] + lm[g3 * IN_DIM + 7];
        eA[i] = __expf(a);
        eB[i] = __expf(b);
    }
    __syncthreads();

    // --- streaming write of this slice ---
    // Vec index i = base + k*256 + tid:
    //   lo4 = i & 63  == tid & 63               -> loop-invariant (register)
    //   hi  = i >> 6  == base/64 + 4k + tid/64  -> 8 values, preloaded
    float4* __restrict__ outv =
        reinterpret_cast<float4*>(out + (size_t)s * RULES);
    const float4* __restrict__ eBv = reinterpret_cast<const float4*>(eB);

    const int   base = slice * VECS_PER_SLICE;
    const float4 b   = eBv[tid & 63];          // hoisted: one LDS.128 total

    float a[ITERS];
    const int hi0 = (base >> 6) + (tid >> 6);
    #pragma unroll
    for (int k = 0; k < ITERS; ++k)
        a[k] = eA[hi0 + 4 * k];                // 8 scalar LDS, then smem done

    #pragma unroll
    for (int k = 0; k < ITERS; ++k) {          // 8 independent store groups
        const int i = base + k * THREADS + tid;
        float4 o;
        o.x = a[k] * b.x;
        o.y = a[k] * b.y;
        o.z = a[k] * b.z;
        o.w = a[k] * b.w;
        outv[i] = o;
    }
}

extern "C" void kernel_launch(void* const* d_in, const int* in_sizes, int n_in,
                              void* d_out, int out_size)
{
    const float* x      = (const float*)d_in[0];  // model_input [512,8]
    const float* center = (const float*)d_in[1];  // [4,8]
    const float* spread = (const float*)d_in[2];  // [4,8]
    // d_in[3] = fs_ind — deterministic base-4 digit table, decoded in-kernel.
    (void)in_sizes; (void)n_in; (void)out_size;

    float* out = (float*)d_out;                   // [512, 65536] f32

    antecedent_kernel<<<NUM_SAM * SLICES, THREADS>>>(x, center, spread, out);
}

// round 12
// speedup vs baseline: 1.0695x; 1.0695x over previous
#include <cuda_runtime.h>
#include <cuda_bf16.h>
#include <cstdint>

// Antecedent firing strengths:
//   out[s][r] = exp( sum_{d=0..7} log_mv[s, digit_d(r), d] )
// digit_d(r) = (r >> 2*(7-d)) & 3  (base-4 expansion == _fuco_frb rows).
//
// Factorization: r = hi*256 + lo (4 digits each, 4^4 = 256):
//   out[s][r] = eA[hi] * eB[lo]
// 512 exps per CTA (128x fewer than naive); fs_ind gather eliminated by
// arithmetic digit decode. Main loop: register-resident eA/eB, 8
// independent FMUL4 + STG.128 groups -> pure streaming stores.
//
// FINAL (R6 config; identical-code samples: kernel 20.38-21.50us,
// dur 23.04-24.61us -> sigma ~0.5us noise). R4-R11 established the
// binder is the fixed 134MB output stream at the path-independent
// chip-level LTS/HBM write ceiling (~6.5 TB/s): invariant to store
// width (v4/v8), cache policy (stcs/plain), grid shape
// (1024/2048/4096), occupancy (57-83%), and hot-loop smem traffic.
// ~94% of the achievable store ceiling.

constexpr int IN_DIM  = 8;
constexpr int NUM_FS  = 4;
constexpr int NUM_SAM = 512;
constexpr int HALF    = 256;     // 4^4
constexpr int RULES   = 65536;   // 4^8
constexpr int THREADS = 256;
constexpr int SLICES  = 8;                        // CTAs per sample
constexpr int VECS    = RULES / 4;                // 16384 float4 per sample
constexpr int VECS_PER_SLICE = VECS / SLICES;     // 2048
constexpr int ITERS   = VECS_PER_SLICE / THREADS; // 8

__global__ __launch_bounds__(THREADS)
void antecedent_kernel(const float* __restrict__ x,      // [512, 8]
                       const float* __restrict__ center, // [4, 8]
                       const float* __restrict__ spread, // [4, 8]
                       float* __restrict__ out)          // [512, 65536]
{
    __shared__ float lm[NUM_FS * IN_DIM];
    __shared__ __align__(16) float eA[HALF];
    __shared__ __align__(16) float eB[HALF];

    const int s     = blockIdx.x >> 3;      // sample
    const int slice = blockIdx.x & 7;       // eighth of the sample's output
    const int tid   = threadIdx.x;

    // --- per-sample log membership table (32 values) ---
    if (tid < NUM_FS * IN_DIM) {
        const int f = tid / IN_DIM;
        const int d = tid % IN_DIM;
        const float xv = x[s * IN_DIM + d];
        const float c  = center[f * IN_DIM + d];
        const float sp = spread[f * IN_DIM + d];
        const float df = xv - c;
        lm[f * IN_DIM + d] = -(df * df) / (2.0f * sp * sp);
    }
    __syncthreads();

    // --- factorized half-sums over 4 digits each ---
    if (tid < HALF) {
        const int i  = tid;
        const int g0 = (i >> 6) & 3;
        const int g1 = (i >> 4) & 3;
        const int g2 = (i >> 2) & 3;
        const int g3 =  i       & 3;
        const float a = lm[g0 * IN_DIM + 0] + lm[g1 * IN_DIM + 1]
                      + lm[g2 * IN_DIM + 2] + lm[g3 * IN_DIM + 3];
        const float b = lm[g0 * IN_DIM + 4] + lm[g1 * IN_DIM + 5]
                      + lm[g2 * IN_DIM + 6] + lm[g3 * IN_DIM + 7];
        eA[i] = __expf(a);
        eB[i] = __expf(b);
    }
    __syncthreads();

    // --- streaming write of this slice ---
    // Vec index i = base + k*256 + tid:
    //   lo4 = i & 63  == tid & 63               -> loop-invariant (register)
    //   hi  = i >> 6  == base/64 + 4k + tid/64  -> 8 values, preloaded
    float4* __restrict__ outv =
        reinterpret_cast<float4*>(out + (size_t)s * RULES);
    const float4* __restrict__ eBv = reinterpret_cast<const float4*>(eB);

    const int   base = slice * VECS_PER_SLICE;
    const float4 b   = eBv[tid & 63];          // hoisted: one LDS.128 total

    float a[ITERS];
    const int hi0 = (base >> 6) + (tid >> 6);
    #pragma unroll
    for (int k = 0; k < ITERS; ++k)
        a[k] = eA[hi0 + 4 * k];                // 8 scalar LDS, then smem done

    #pragma unroll
    for (int k = 0; k < ITERS; ++k) {          // 8 independent store groups
        const int i = base + k * THREADS + tid;
        float4 o;
        o.x = a[k] * b.x;
        o.y = a[k] * b.y;
        o.z = a[k] * b.z;
        o.w = a[k] * b.w;
        outv[i] = o;
    }
}

extern "C" void kernel_launch(void* const* d_in, const int* in_sizes, int n_in,
                              void* d_out, int out_size)
{
    const float* x      = (const float*)d_in[0];  // model_input [512,8]
    const float* center = (const float*)d_in[1];  // [4,8]
    const float* spread = (const float*)d_in[2];  // [4,8]
    // d_in[3] = fs_ind — deterministic base-4 digit table, decoded in-kernel.
    (void)in_sizes; (void)n_in; (void)out_size;

    float* out = (float*)d_out;                   // [512, 65536] f32

    antecedent_kernel<<<NUM_SAM * SLICES, THREADS>>>(x, center, spread, out);
}